// round 14
// baseline (speedup 1.0000x reference)
#include <cuda_runtime.h>
#include <cuda_fp16.h>
#include <cstdint>
#include <cstddef>

#define NB 4
#define NH 16
#define NS 2048
#define ND 64
#define KPAD 72
#define QTILE 256
// smem layout
#define VH_OFF 9216
#define QS_OFF 18432
#define ST_OFF 83968            // 18432 + 65536 (qs)
#define SMEM_TOTAL 149504       // ST_OFF + 2*32768 staging

static __device__ __forceinline__ uint32_t sptr(const void* p) {
    return (uint32_t)__cvta_generic_to_shared(p);
}
static __device__ __forceinline__ void cpasync16(uint32_t dst, const void* src) {
    asm volatile("cp.async.cg.shared.global [%0], [%1], 16;" :: "r"(dst), "l"(src));
}
static __device__ __forceinline__ void ldsm4(uint32_t& r0, uint32_t& r1, uint32_t& r2, uint32_t& r3, uint32_t a) {
    asm volatile("ldmatrix.sync.aligned.m8n8.x4.shared.b16 {%0,%1,%2,%3},[%4];"
                 : "=r"(r0), "=r"(r1), "=r"(r2), "=r"(r3) : "r"(a));
}
static __device__ __forceinline__ void ldsm4t(uint32_t& r0, uint32_t& r1, uint32_t& r2, uint32_t& r3, uint32_t a) {
    asm volatile("ldmatrix.sync.aligned.m8n8.x4.trans.shared.b16 {%0,%1,%2,%3},[%4];"
                 : "=r"(r0), "=r"(r1), "=r"(r2), "=r"(r3) : "r"(a));
}
static __device__ __forceinline__ void mma16816(float* d, const uint32_t* a, uint32_t b0, uint32_t b1) {
    asm volatile(
        "mma.sync.aligned.m16n8k16.row.col.f32.f16.f16.f32 "
        "{%0,%1,%2,%3},{%4,%5,%6,%7},{%8,%9},{%0,%1,%2,%3};"
        : "+f"(d[0]), "+f"(d[1]), "+f"(d[2]), "+f"(d[3])
        : "r"(a[0]), "r"(a[1]), "r"(a[2]), "r"(a[3]), "r"(b0), "r"(b1));
}
static __device__ __forceinline__ uint32_t pack2(float a, float b) {
    __half2 h = __halves2half2(__float2half_rn(a), __float2half_rn(b));
    return *(uint32_t*)&h;
}
static __device__ __forceinline__ void h4store(__half* dst, float4 v) {
    __half2 a = __halves2half2(__float2half_rn(v.x), __float2half_rn(v.y));
    __half2 b = __halves2half2(__float2half_rn(v.z), __float2half_rn(v.w));
    ((__half2*)dst)[0] = a;
    ((__half2*)dst)[1] = b;
}
static __device__ __forceinline__ void stcs2(float* p, float a, float b) {
    asm volatile("st.global.cs.v2.f32 [%0], {%1,%2};" :: "l"(p), "f"(a), "f"(b) : "memory");
}
static __device__ __forceinline__ void stcs4(float* p, float4 v) {
    asm volatile("st.global.cs.v4.f32 [%0], {%1,%2,%3,%4};"
                 :: "l"(p), "f"(v.x), "f"(v.y), "f"(v.z), "f"(v.w) : "memory");
}

// Two-loop fused attention, plain fp16 operands, fp32 accumulate, q-tile 256.
// loop1: Z[row] = sum exp(s) (K staged only); loop2: normalized P + O = P.V.
// cp.async double-buffered staging, streaming stores for attn.
// grid(64,8), block 512, 1 CTA/SM (16 warps).
__global__ __launch_bounds__(512, 1) void attn_fused(const float* __restrict__ Q,
                                                     const float* __restrict__ K,
                                                     const float* __restrict__ V,
                                                     float* __restrict__ ctx,
                                                     float* __restrict__ attn) {
    extern __shared__ char smem[];
    __half* kh = (__half*)smem;                    // 64 x KPAD
    __half* vh = (__half*)(smem + VH_OFF);         // 64 x KPAD
    float* qs = (float*)(smem + QS_OFF);           // 256 x 64 fp32
    const uint32_t stage_base = sptr(smem + ST_OFF);

    const int bh = blockIdx.x;
    const int qt = (int)gridDim.y - 1 - (int)blockIdx.y;  // heavy tiles first
    const int r0 = qt << 8;
    const float* Qb = Q + ((size_t)bh * NS + r0) * ND;
    const float* Kb = K + (size_t)bh * NS * ND;
    const float* Vb = V + (size_t)bh * NS * ND;
    const int tid = threadIdx.x;
    const int nsteps = (r0 + QTILE) >> 6;

    // load Q (scaled) into qs; prefetch K tile 0 into staging buffer 0
    for (int i = tid; i < 4096; i += 512) {
        float4 v = ((const float4*)Qb)[i];
        v.x *= 0.125f; v.y *= 0.125f; v.z *= 0.125f; v.w *= 0.125f;
        ((float4*)qs)[i] = v;
    }
    {
        const float4* kg = (const float4*)Kb;
        for (int i = tid; i < 1024; i += 512)
            cpasync16(stage_base + i * 16, kg + i);
        asm volatile("cp.async.commit_group;");
    }
    __syncthreads();

    const int w = tid >> 5, L = tid & 31, g2 = L >> 2, t4 = L & 3, g3 = L >> 3, lr = L & 7;

    uint32_t Ah[4][4];
    {
        const int rA = (w << 4) + g2;
#pragma unroll
        for (int kc = 0; kc < 4; kc++) {
            int c0 = (kc << 4) + (t4 << 1);
            Ah[kc][0] = pack2(qs[rA * 64 + c0],           qs[rA * 64 + c0 + 1]);
            Ah[kc][1] = pack2(qs[(rA + 8) * 64 + c0],     qs[(rA + 8) * 64 + c0 + 1]);
            Ah[kc][2] = pack2(qs[rA * 64 + c0 + 8],       qs[rA * 64 + c0 + 9]);
            Ah[kc][3] = pack2(qs[(rA + 8) * 64 + c0 + 8], qs[(rA + 8) * 64 + c0 + 9]);
        }
    }

    const int row0 = r0 + (w << 4) + g2;
    const int row1 = row0 + 8;
    const int key_l = lr + ((g3 & 1) << 3);
    const int d_l = (g3 & 2) << 2;

    // ------------------ loop 1: Z only (K staged, no V, no stores) -----------
    float zs0 = 0.f, zs1 = 0.f;
    for (int s = 0; s < nsteps; s++) {
        if (s + 1 < nsteps) {
            const int k1 = (s + 1) << 6;
            const uint32_t sb = stage_base + ((s + 1) & 1) * 32768;
            const float4* kg = (const float4*)(Kb + (size_t)k1 * ND);
            for (int i = tid; i < 1024; i += 512)
                cpasync16(sb + i * 16, kg + i);
            asm volatile("cp.async.commit_group;");
            asm volatile("cp.async.wait_group 1;");
        } else {
            asm volatile("cp.async.wait_group 0;");
        }
        __syncthreads();

        {
            const float4* kf = (const float4*)(smem + ST_OFF + (s & 1) * 32768);
            for (int i = tid; i < 1024; i += 512) {
                int key = i >> 4, d = (i & 15) << 2;
                h4store(kh + key * KPAD + d, kf[i]);
            }
        }
        __syncthreads();

        const int k0 = s << 6;
#pragma unroll
        for (int np = 0; np < 4; np++) {
            float SvA[8] = {0.f, 0.f, 0.f, 0.f, 0.f, 0.f, 0.f, 0.f};
            float SvB[8] = {0.f, 0.f, 0.f, 0.f, 0.f, 0.f, 0.f, 0.f};
#pragma unroll
            for (int kc = 0; kc < 4; kc++) {
                uint32_t b0, b1, b2, b3;
                uint32_t off = (uint32_t)((np * 16 + key_l) * KPAD + (kc << 4) + d_l);
                ldsm4(b0, b1, b2, b3, sptr(kh + off));
                float* dst = (kc < 2) ? SvA : SvB;
                mma16816(dst,     Ah[kc], b0, b2);
                mma16816(dst + 4, Ah[kc], b1, b3);
            }
            const int kb = k0 + (np << 4) + (t4 << 1);
            if (kb + 9 <= row0) {  // whole group visible for both rows
                zs0 += __expf(SvA[0] + SvB[0]) + __expf(SvA[1] + SvB[1])
                     + __expf(SvA[4] + SvB[4]) + __expf(SvA[5] + SvB[5]);
                zs1 += __expf(SvA[2] + SvB[2]) + __expf(SvA[3] + SvB[3])
                     + __expf(SvA[6] + SvB[6]) + __expf(SvA[7] + SvB[7]);
            } else {
                float p;
                p = (kb     <= row0) ? __expf(SvA[0] + SvB[0]) : 0.f; zs0 += p;
                p = (kb + 1 <= row0) ? __expf(SvA[1] + SvB[1]) : 0.f; zs0 += p;
                p = (kb     <= row1) ? __expf(SvA[2] + SvB[2]) : 0.f; zs1 += p;
                p = (kb + 1 <= row1) ? __expf(SvA[3] + SvB[3]) : 0.f; zs1 += p;
                p = (kb + 8 <= row0) ? __expf(SvA[4] + SvB[4]) : 0.f; zs0 += p;
                p = (kb + 9 <= row0) ? __expf(SvA[5] + SvB[5]) : 0.f; zs0 += p;
                p = (kb + 8 <= row1) ? __expf(SvA[6] + SvB[6]) : 0.f; zs1 += p;
                p = (kb + 9 <= row1) ? __expf(SvA[7] + SvB[7]) : 0.f; zs1 += p;
            }
        }
    }

    zs0 += __shfl_xor_sync(0xffffffffu, zs0, 1);
    zs0 += __shfl_xor_sync(0xffffffffu, zs0, 2);
    zs1 += __shfl_xor_sync(0xffffffffu, zs1, 1);
    zs1 += __shfl_xor_sync(0xffffffffu, zs1, 2);
    const float zi0 = 1.0f / zs0;
    const float zi1 = 1.0f / zs1;

    float* arow0 = attn + ((size_t)bh * NS + row0) * NS;
    float* arow1 = attn + ((size_t)bh * NS + row1) * NS;

    float Ov[8][4];
#pragma unroll
    for (int i = 0; i < 8; i++)
#pragma unroll
        for (int j = 0; j < 4; j++) Ov[i][j] = 0.f;

    // prefetch K+V tile 0 for loop 2
    {
        const float4* kg = (const float4*)Kb;
        const float4* vg = (const float4*)Vb;
        for (int i = tid; i < 1024; i += 512) {
            cpasync16(stage_base + i * 16, kg + i);
            cpasync16(stage_base + 16384 + i * 16, vg + i);
        }
        asm volatile("cp.async.commit_group;");
    }

    // ------------- loop 2: emit normalized P, accumulate O -------------------
    for (int s = 0; s < nsteps; s++) {
        if (s + 1 < nsteps) {
            const int k1 = (s + 1) << 6;
            const uint32_t sb = stage_base + ((s + 1) & 1) * 32768;
            const float4* kg = (const float4*)(Kb + (size_t)k1 * ND);
            const float4* vg = (const float4*)(Vb + (size_t)k1 * ND);
            for (int i = tid; i < 1024; i += 512) {
                cpasync16(sb + i * 16, kg + i);
                cpasync16(sb + 16384 + i * 16, vg + i);
            }
            asm volatile("cp.async.commit_group;");
            asm volatile("cp.async.wait_group 1;");
        } else {
            asm volatile("cp.async.wait_group 0;");
        }
        __syncthreads();

        {
            const float4* kf = (const float4*)(smem + ST_OFF + (s & 1) * 32768);
            const float4* vf = kf + 1024;
            for (int i = tid; i < 1024; i += 512) {
                int key = i >> 4, d = (i & 15) << 2;
                h4store(kh + key * KPAD + d, kf[i]);
                h4store(vh + key * KPAD + d, vf[i]);
            }
        }
        __syncthreads();

        const int k0 = s << 6;
#pragma unroll
        for (int np = 0; np < 4; np++) {
            float Sv[8] = {0.f, 0.f, 0.f, 0.f, 0.f, 0.f, 0.f, 0.f};
#pragma unroll
            for (int kc = 0; kc < 4; kc++) {
                uint32_t b0, b1, b2, b3;
                uint32_t off = (uint32_t)((np * 16 + key_l) * KPAD + (kc << 4) + d_l);
                ldsm4(b0, b1, b2, b3, sptr(kh + off));
                mma16816(Sv,     Ah[kc], b0, b2);
                mma16816(Sv + 4, Ah[kc], b1, b3);
            }
            const int kb = k0 + (np << 4) + (t4 << 1);
            float p0, p1, p2, p3, p4, p5, p6, p7;
            if (kb + 9 <= row0) {  // fully visible group
                p0 = __expf(Sv[0]) * zi0;
                p1 = __expf(Sv[1]) * zi0;
                p2 = __expf(Sv[2]) * zi1;
                p3 = __expf(Sv[3]) * zi1;
                p4 = __expf(Sv[4]) * zi0;
                p5 = __expf(Sv[5]) * zi0;
                p6 = __expf(Sv[6]) * zi1;
                p7 = __expf(Sv[7]) * zi1;
            } else {
                p0 = (kb     <= row0) ? __expf(Sv[0]) * zi0 : 0.f;
                p1 = (kb + 1 <= row0) ? __expf(Sv[1]) * zi0 : 0.f;
                p2 = (kb     <= row1) ? __expf(Sv[2]) * zi1 : 0.f;
                p3 = (kb + 1 <= row1) ? __expf(Sv[3]) * zi1 : 0.f;
                p4 = (kb + 8 <= row0) ? __expf(Sv[4]) * zi0 : 0.f;
                p5 = (kb + 9 <= row0) ? __expf(Sv[5]) * zi0 : 0.f;
                p6 = (kb + 8 <= row1) ? __expf(Sv[6]) * zi1 : 0.f;
                p7 = (kb + 9 <= row1) ? __expf(Sv[7]) * zi1 : 0.f;
            }

            stcs2(arow0 + kb,     p0, p1);
            stcs2(arow1 + kb,     p2, p3);
            stcs2(arow0 + kb + 8, p4, p5);
            stcs2(arow1 + kb + 8, p6, p7);

            uint32_t Ph[4];
            Ph[0] = pack2(p0, p1);
            Ph[1] = pack2(p2, p3);
            Ph[2] = pack2(p4, p5);
            Ph[3] = pack2(p6, p7);

#pragma unroll
            for (int dd = 0; dd < 4; dd++) {
                uint32_t v0, v1, v2, v3;
                uint32_t off = (uint32_t)((np * 16 + key_l) * KPAD + (dd << 4) + d_l);
                ldsm4t(v0, v1, v2, v3, sptr(vh + off));
                mma16816(Ov[2 * dd],     Ph, v0, v1);
                mma16816(Ov[2 * dd + 1], Ph, v2, v3);
            }
        }
    }

    // write context (P already normalized)
    {
        float* crow0 = ctx + ((size_t)bh * NS + row0) * ND;
        float* crow1 = ctx + ((size_t)bh * NS + row1) * ND;
#pragma unroll
        for (int dt = 0; dt < 8; dt++) {
            int c = (dt << 3) + (t4 << 1);
            *(float2*)(crow0 + c) = make_float2(Ov[dt][0], Ov[dt][1]);
            *(float2*)(crow1 + c) = make_float2(Ov[dt][2], Ov[dt][3]);
        }
    }

    // zero-fill masked region beyond the causal band (streaming stores)
    {
        const int ks = (qt + 1) << 8;
        if (ks < NS) {
            const int width4 = (NS - ks) >> 2;
            float4 z4 = make_float4(0.f, 0.f, 0.f, 0.f);
            float* abase = attn + ((size_t)bh * NS + r0) * NS + ks;
            const int total = QTILE * width4;
            for (int i = tid; i < total; i += 512) {
                int row = i / width4;
                int c = i - row * width4;
                stcs4(abase + (size_t)row * NS + (c << 2), z4);
            }
        }
    }
}

extern "C" void kernel_launch(void* const* d_in, const int* in_sizes, int n_in,
                              void* d_out, int out_size) {
    const float* Q = (const float*)d_in[0];
    const float* K = (const float*)d_in[1];
    const float* V = (const float*)d_in[2];
    float* ctx = (float*)d_out;
    float* attn = (float*)d_out + (size_t)NB * NH * NS * ND;

    static bool attr_set = false;
    if (!attr_set) {
        cudaFuncSetAttribute(attn_fused, cudaFuncAttributeMaxDynamicSharedMemorySize, SMEM_TOTAL);
        attr_set = true;
    }

    dim3 grid(NB * NH, NS / QTILE);
    dim3 block(512);
    attn_fused<<<grid, block, SMEM_TOTAL>>>(Q, K, V, ctx, attn);
}

// round 15
// speedup vs baseline: 1.0620x; 1.0620x over previous
#include <cuda_runtime.h>
#include <cuda_fp16.h>
#include <cstdint>
#include <cstddef>

#define NB 4
#define NH 16
#define NS 2048
#define ND 64
#define KPAD 72
#define STAGE_OFF 18432   // after 2 fp16 buffers of 64*KPAD*2 = 9216 B each
#define QSCALE 0.18033688011112042f   // 0.125 * log2(e): puts scores in log2 domain

static __device__ __forceinline__ uint32_t sptr(const void* p) {
    return (uint32_t)__cvta_generic_to_shared(p);
}
static __device__ __forceinline__ void cpasync16(uint32_t dst, const void* src) {
    asm volatile("cp.async.cg.shared.global [%0], [%1], 16;" :: "r"(dst), "l"(src));
}
static __device__ __forceinline__ float ex2(float x) {
    float r;
    asm("ex2.approx.ftz.f32 %0, %1;" : "=f"(r) : "f"(x));
    return r;
}
static __device__ __forceinline__ void ldsm4(uint32_t& r0, uint32_t& r1, uint32_t& r2, uint32_t& r3, uint32_t a) {
    asm volatile("ldmatrix.sync.aligned.m8n8.x4.shared.b16 {%0,%1,%2,%3},[%4];"
                 : "=r"(r0), "=r"(r1), "=r"(r2), "=r"(r3) : "r"(a));
}
static __device__ __forceinline__ void ldsm4t(uint32_t& r0, uint32_t& r1, uint32_t& r2, uint32_t& r3, uint32_t a) {
    asm volatile("ldmatrix.sync.aligned.m8n8.x4.trans.shared.b16 {%0,%1,%2,%3},[%4];"
                 : "=r"(r0), "=r"(r1), "=r"(r2), "=r"(r3) : "r"(a));
}
static __device__ __forceinline__ void mma16816(float* d, const uint32_t* a, uint32_t b0, uint32_t b1) {
    asm volatile(
        "mma.sync.aligned.m16n8k16.row.col.f32.f16.f16.f32 "
        "{%0,%1,%2,%3},{%4,%5,%6,%7},{%8,%9},{%0,%1,%2,%3};"
        : "+f"(d[0]), "+f"(d[1]), "+f"(d[2]), "+f"(d[3])
        : "r"(a[0]), "r"(a[1]), "r"(a[2]), "r"(a[3]), "r"(b0), "r"(b1));
}
static __device__ __forceinline__ uint32_t pack2(float a, float b) {
    __half2 h = __halves2half2(__float2half_rn(a), __float2half_rn(b));
    return *(uint32_t*)&h;
}
static __device__ __forceinline__ void h4store(__half* dst, float4 v) {
    __half2 a = __halves2half2(__float2half_rn(v.x), __float2half_rn(v.y));
    __half2 b = __halves2half2(__float2half_rn(v.z), __float2half_rn(v.w));
    ((__half2*)dst)[0] = a;
    ((__half2*)dst)[1] = b;
}
static __device__ __forceinline__ void stcs2(float* p, float a, float b) {
    asm volatile("st.global.cs.v2.f32 [%0], {%1,%2};" :: "l"(p), "f"(a), "f"(b) : "memory");
}
static __device__ __forceinline__ void stcs4(float* p, float4 v) {
    asm volatile("st.global.cs.v4.f32 [%0], {%1,%2,%3,%4};"
                 :: "l"(p), "f"(v.x), "f"(v.y), "f"(v.z), "f"(v.w) : "memory");
}

// Two-loop fused attention, plain fp16 operands, fp32 accumulate.
// Scores computed in log2 domain (Q pre-scaled by 0.125*log2e):
//   loop1: Z[row] = sum ex2(s);  loop2: P = ex2(s + log2(1/Z)), O = P.V
// cp.async double-buffered staging, streaming attn stores.
// grid(64,16), block 256, 2 CTAs/SM.
__global__ __launch_bounds__(256, 2) void attn_fused(const float* __restrict__ Q,
                                                     const float* __restrict__ K,
                                                     const float* __restrict__ V,
                                                     float* __restrict__ ctx,
                                                     float* __restrict__ attn) {
    extern __shared__ char smem[];
    __half* kh = (__half*)smem;                    // 64 x KPAD
    __half* vh = kh + 64 * KPAD;                   // 64 x KPAD
    float* qs = (float*)(smem + STAGE_OFF + 32768);
    const uint32_t stage_base = sptr(smem + STAGE_OFF);

    const int bh = blockIdx.x;
    const int qt = (int)gridDim.y - 1 - (int)blockIdx.y;  // heavy tiles first
    const int r0 = qt << 7;
    const float* Qb = Q + ((size_t)bh * NS + r0) * ND;
    const float* Kb = K + (size_t)bh * NS * ND;
    const float* Vb = V + (size_t)bh * NS * ND;
    const int tid = threadIdx.x;
    const int nsteps = (r0 + 128) >> 6;

    // load Q (scaled into log2 domain) into qs; prefetch K tile 0
    for (int i = tid; i < 2048; i += 256) {
        float4 v = ((const float4*)Qb)[i];
        v.x *= QSCALE; v.y *= QSCALE; v.z *= QSCALE; v.w *= QSCALE;
        ((float4*)qs)[i] = v;
    }
    {
        const float4* kg = (const float4*)Kb;
        for (int i = tid; i < 1024; i += 256)
            cpasync16(stage_base + i * 16, kg + i);
        asm volatile("cp.async.commit_group;");
    }
    __syncthreads();

    const int w = tid >> 5, L = tid & 31, g2 = L >> 2, t4 = L & 3, g3 = L >> 3, lr = L & 7;

    uint32_t Ah[4][4];
    {
        const int rA = (w << 4) + g2;
#pragma unroll
        for (int kc = 0; kc < 4; kc++) {
            int c0 = (kc << 4) + (t4 << 1);
            Ah[kc][0] = pack2(qs[rA * 64 + c0],           qs[rA * 64 + c0 + 1]);
            Ah[kc][1] = pack2(qs[(rA + 8) * 64 + c0],     qs[(rA + 8) * 64 + c0 + 1]);
            Ah[kc][2] = pack2(qs[rA * 64 + c0 + 8],       qs[rA * 64 + c0 + 9]);
            Ah[kc][3] = pack2(qs[(rA + 8) * 64 + c0 + 8], qs[(rA + 8) * 64 + c0 + 9]);
        }
    }
    __syncthreads();  // qs consumed; staging buffer 1 may be overwritten

    const int row0 = r0 + (w << 4) + g2;
    const int row1 = row0 + 8;
    const int key_l = lr + ((g3 & 1) << 3);
    const int d_l = (g3 & 2) << 2;

    // ------------------ loop 1: Z only (K staged, no V, no stores) -----------
    float zs0 = 0.f, zs1 = 0.f;
    for (int s = 0; s < nsteps; s++) {
        if (s + 1 < nsteps) {
            const int k1 = (s + 1) << 6;
            const uint32_t sb = stage_base + ((s + 1) & 1) * 32768;
            const float4* kg = (const float4*)(Kb + (size_t)k1 * ND);
            for (int i = tid; i < 1024; i += 256)
                cpasync16(sb + i * 16, kg + i);
            asm volatile("cp.async.commit_group;");
            asm volatile("cp.async.wait_group 1;");
        } else {
            asm volatile("cp.async.wait_group 0;");
        }
        __syncthreads();

        {
            const float4* kf = (const float4*)(smem + STAGE_OFF + (s & 1) * 32768);
            for (int i = tid; i < 1024; i += 256) {
                int key = i >> 4, d = (i & 15) << 2;
                h4store(kh + key * KPAD + d, kf[i]);
            }
        }
        __syncthreads();

        const int k0 = s << 6;
#pragma unroll
        for (int np = 0; np < 4; np++) {
            float SvA[8] = {0.f, 0.f, 0.f, 0.f, 0.f, 0.f, 0.f, 0.f};
            float SvB[8] = {0.f, 0.f, 0.f, 0.f, 0.f, 0.f, 0.f, 0.f};
#pragma unroll
            for (int kc = 0; kc < 4; kc++) {
                uint32_t b0, b1, b2, b3;
                uint32_t off = (uint32_t)((np * 16 + key_l) * KPAD + (kc << 4) + d_l);
                ldsm4(b0, b1, b2, b3, sptr(kh + off));
                float* dst = (kc < 2) ? SvA : SvB;
                mma16816(dst,     Ah[kc], b0, b2);
                mma16816(dst + 4, Ah[kc], b1, b3);
            }
            const int kb = k0 + (np << 4) + (t4 << 1);
            if (kb + 9 <= row0) {  // whole group visible for both rows
                zs0 += ex2(SvA[0] + SvB[0]) + ex2(SvA[1] + SvB[1])
                     + ex2(SvA[4] + SvB[4]) + ex2(SvA[5] + SvB[5]);
                zs1 += ex2(SvA[2] + SvB[2]) + ex2(SvA[3] + SvB[3])
                     + ex2(SvA[6] + SvB[6]) + ex2(SvA[7] + SvB[7]);
            } else {
                float p;
                p = (kb     <= row0) ? ex2(SvA[0] + SvB[0]) : 0.f; zs0 += p;
                p = (kb + 1 <= row0) ? ex2(SvA[1] + SvB[1]) : 0.f; zs0 += p;
                p = (kb     <= row1) ? ex2(SvA[2] + SvB[2]) : 0.f; zs1 += p;
                p = (kb + 1 <= row1) ? ex2(SvA[3] + SvB[3]) : 0.f; zs1 += p;
                p = (kb + 8 <= row0) ? ex2(SvA[4] + SvB[4]) : 0.f; zs0 += p;
                p = (kb + 9 <= row0) ? ex2(SvA[5] + SvB[5]) : 0.f; zs0 += p;
                p = (kb + 8 <= row1) ? ex2(SvA[6] + SvB[6]) : 0.f; zs1 += p;
                p = (kb + 9 <= row1) ? ex2(SvA[7] + SvB[7]) : 0.f; zs1 += p;
            }
        }
    }

    zs0 += __shfl_xor_sync(0xffffffffu, zs0, 1);
    zs0 += __shfl_xor_sync(0xffffffffu, zs0, 2);
    zs1 += __shfl_xor_sync(0xffffffffu, zs1, 1);
    zs1 += __shfl_xor_sync(0xffffffffu, zs1, 2);
    const float l2z0 = -__log2f(zs0);   // log2(1/Z)
    const float l2z1 = -__log2f(zs1);

    float* arow0 = attn + ((size_t)bh * NS + row0) * NS;
    float* arow1 = attn + ((size_t)bh * NS + row1) * NS;

    float Ov[8][4];
#pragma unroll
    for (int i = 0; i < 8; i++)
#pragma unroll
        for (int j = 0; j < 4; j++) Ov[i][j] = 0.f;

    // prefetch K+V tile 0 for loop 2
    {
        const float4* kg = (const float4*)Kb;
        const float4* vg = (const float4*)Vb;
        for (int i = tid; i < 1024; i += 256) {
            cpasync16(stage_base + i * 16, kg + i);
            cpasync16(stage_base + 16384 + i * 16, vg + i);
        }
        asm volatile("cp.async.commit_group;");
    }

    // ------------- loop 2: emit normalized P, accumulate O -------------------
    for (int s = 0; s < nsteps; s++) {
        if (s + 1 < nsteps) {
            const int k1 = (s + 1) << 6;
            const uint32_t sb = stage_base + ((s + 1) & 1) * 32768;
            const float4* kg = (const float4*)(Kb + (size_t)k1 * ND);
            const float4* vg = (const float4*)(Vb + (size_t)k1 * ND);
            for (int i = tid; i < 1024; i += 256) {
                cpasync16(sb + i * 16, kg + i);
                cpasync16(sb + 16384 + i * 16, vg + i);
            }
            asm volatile("cp.async.commit_group;");
            asm volatile("cp.async.wait_group 1;");
        } else {
            asm volatile("cp.async.wait_group 0;");
        }
        __syncthreads();

        {
            const float4* kf = (const float4*)(smem + STAGE_OFF + (s & 1) * 32768);
            const float4* vf = kf + 1024;
            for (int i = tid; i < 1024; i += 256) {
                int key = i >> 4, d = (i & 15) << 2;
                h4store(kh + key * KPAD + d, kf[i]);
                h4store(vh + key * KPAD + d, vf[i]);
            }
        }
        __syncthreads();

        const int k0 = s << 6;
#pragma unroll
        for (int np = 0; np < 4; np++) {
            float Sv[8];
            Sv[0] = Sv[1] = l2z0; Sv[2] = Sv[3] = l2z1;
            Sv[4] = Sv[5] = l2z0; Sv[6] = Sv[7] = l2z1;
#pragma unroll
            for (int kc = 0; kc < 4; kc++) {
                uint32_t b0, b1, b2, b3;
                uint32_t off = (uint32_t)((np * 16 + key_l) * KPAD + (kc << 4) + d_l);
                ldsm4(b0, b1, b2, b3, sptr(kh + off));
                mma16816(Sv,     Ah[kc], b0, b2);
                mma16816(Sv + 4, Ah[kc], b1, b3);
            }
            const int kb = k0 + (np << 4) + (t4 << 1);
            float p0, p1, p2, p3, p4, p5, p6, p7;
            if (kb + 9 <= row0) {  // fully visible group
                p0 = ex2(Sv[0]); p1 = ex2(Sv[1]);
                p2 = ex2(Sv[2]); p3 = ex2(Sv[3]);
                p4 = ex2(Sv[4]); p5 = ex2(Sv[5]);
                p6 = ex2(Sv[6]); p7 = ex2(Sv[7]);
            } else {
                p0 = (kb     <= row0) ? ex2(Sv[0]) : 0.f;
                p1 = (kb + 1 <= row0) ? ex2(Sv[1]) : 0.f;
                p2 = (kb     <= row1) ? ex2(Sv[2]) : 0.f;
                p3 = (kb + 1 <= row1) ? ex2(Sv[3]) : 0.f;
                p4 = (kb + 8 <= row0) ? ex2(Sv[4]) : 0.f;
                p5 = (kb + 9 <= row0) ? ex2(Sv[5]) : 0.f;
                p6 = (kb + 8 <= row1) ? ex2(Sv[6]) : 0.f;
                p7 = (kb + 9 <= row1) ? ex2(Sv[7]) : 0.f;
            }

            stcs2(arow0 + kb,     p0, p1);
            stcs2(arow1 + kb,     p2, p3);
            stcs2(arow0 + kb + 8, p4, p5);
            stcs2(arow1 + kb + 8, p6, p7);

            uint32_t Ph[4];
            Ph[0] = pack2(p0, p1);
            Ph[1] = pack2(p2, p3);
            Ph[2] = pack2(p4, p5);
            Ph[3] = pack2(p6, p7);

#pragma unroll
            for (int dd = 0; dd < 4; dd++) {
                uint32_t v0, v1, v2, v3;
                uint32_t off = (uint32_t)((np * 16 + key_l) * KPAD + (dd << 4) + d_l);
                ldsm4t(v0, v1, v2, v3, sptr(vh + off));
                mma16816(Ov[2 * dd],     Ph, v0, v1);
                mma16816(Ov[2 * dd + 1], Ph, v2, v3);
            }
        }
    }

    // write context (P already normalized)
    {
        float* crow0 = ctx + ((size_t)bh * NS + row0) * ND;
        float* crow1 = ctx + ((size_t)bh * NS + row1) * ND;
#pragma unroll
        for (int dt = 0; dt < 8; dt++) {
            int c = (dt << 3) + (t4 << 1);
            *(float2*)(crow0 + c) = make_float2(Ov[dt][0], Ov[dt][1]);
            *(float2*)(crow1 + c) = make_float2(Ov[dt][2], Ov[dt][3]);
        }
    }

    // zero-fill masked region beyond the causal band (streaming stores)
    {
        const int ks = (qt + 1) << 7;
        if (ks < NS) {
            const int width4 = (NS - ks) >> 2;
            float4 z4 = make_float4(0.f, 0.f, 0.f, 0.f);
            float* abase = attn + ((size_t)bh * NS + r0) * NS + ks;
            const int total = 128 * width4;
            for (int i = tid; i < total; i += 256) {
                int row = i / width4;
                int c = i - row * width4;
                stcs4(abase + (size_t)row * NS + (c << 2), z4);
            }
        }
    }
}

extern "C" void kernel_launch(void* const* d_in, const int* in_sizes, int n_in,
                              void* d_out, int out_size) {
    const float* Q = (const float*)d_in[0];
    const float* K = (const float*)d_in[1];
    const float* V = (const float*)d_in[2];
    float* ctx = (float*)d_out;
    float* attn = (float*)d_out + (size_t)NB * NH * NS * ND;

    static bool attr_set = false;
    if (!attr_set) {
        cudaFuncSetAttribute(attn_fused, cudaFuncAttributeMaxDynamicSharedMemorySize, 83968);
        attr_set = true;
    }

    dim3 grid(NB * NH, NS / 128);
    dim3 block(256);
    attn_fused<<<grid, block, 83968>>>(Q, K, V, ctx, attn);
}

// round 16
// speedup vs baseline: 1.1090x; 1.0443x over previous
#include <cuda_runtime.h>
#include <cuda_fp16.h>
#include <cstdint>
#include <cstddef>

#define NB 4
#define NH 16
#define NS 2048
#define ND 64
#define KPAD 72
#define QSCALE 0.18033688011112042f   // 0.125 * log2(e): scores in log2 domain

// fp16 K/V scratch, padded to 72 halves per row (144 B = 9 x 16B chunks)
__device__ __half g_kh[(size_t)NB * NH * NS * KPAD];
__device__ __half g_vh[(size_t)NB * NH * NS * KPAD];

static __device__ __forceinline__ uint32_t sptr(const void* p) {
    return (uint32_t)__cvta_generic_to_shared(p);
}
static __device__ __forceinline__ void cpasync16(uint32_t dst, const void* src) {
    asm volatile("cp.async.cg.shared.global [%0], [%1], 16;" :: "r"(dst), "l"(src));
}
static __device__ __forceinline__ float ex2(float x) {
    float r;
    asm("ex2.approx.ftz.f32 %0, %1;" : "=f"(r) : "f"(x));
    return r;
}
static __device__ __forceinline__ void ldsm4(uint32_t& r0, uint32_t& r1, uint32_t& r2, uint32_t& r3, uint32_t a) {
    asm volatile("ldmatrix.sync.aligned.m8n8.x4.shared.b16 {%0,%1,%2,%3},[%4];"
                 : "=r"(r0), "=r"(r1), "=r"(r2), "=r"(r3) : "r"(a));
}
static __device__ __forceinline__ void ldsm4t(uint32_t& r0, uint32_t& r1, uint32_t& r2, uint32_t& r3, uint32_t a) {
    asm volatile("ldmatrix.sync.aligned.m8n8.x4.trans.shared.b16 {%0,%1,%2,%3},[%4];"
                 : "=r"(r0), "=r"(r1), "=r"(r2), "=r"(r3) : "r"(a));
}
static __device__ __forceinline__ void mma16816(float* d, const uint32_t* a, uint32_t b0, uint32_t b1) {
    asm volatile(
        "mma.sync.aligned.m16n8k16.row.col.f32.f16.f16.f32 "
        "{%0,%1,%2,%3},{%4,%5,%6,%7},{%8,%9},{%0,%1,%2,%3};"
        : "+f"(d[0]), "+f"(d[1]), "+f"(d[2]), "+f"(d[3])
        : "r"(a[0]), "r"(a[1]), "r"(a[2]), "r"(a[3]), "r"(b0), "r"(b1));
}
static __device__ __forceinline__ uint32_t pack2(float a, float b) {
    __half2 h = __halves2half2(__float2half_rn(a), __float2half_rn(b));
    return *(uint32_t*)&h;
}
static __device__ __forceinline__ void stcs2(float* p, float a, float b) {
    asm volatile("st.global.cs.v2.f32 [%0], {%1,%2};" :: "l"(p), "f"(a), "f"(b) : "memory");
}
static __device__ __forceinline__ void stcs4(float* p, float4 v) {
    asm volatile("st.global.cs.v4.f32 [%0], {%1,%2,%3,%4};"
                 :: "l"(p), "f"(v.x), "f"(v.y), "f"(v.z), "f"(v.w) : "memory");
}

// ---- pre-pass: fp32 K/V -> fp16 padded scratch ------------------------------
__global__ __launch_bounds__(256) void cvt_kv(const float* __restrict__ K,
                                              const float* __restrict__ V) {
    const int per_tensor = NB * NH * NS * (ND / 4);   // float4 groups = 2097152
    int idx = blockIdx.x * 256 + threadIdx.x;
    const float* src;
    __half* dst;
    int g;
    if (idx < per_tensor) { src = K; dst = g_kh; g = idx; }
    else                  { src = V; dst = g_vh; g = idx - per_tensor; }
    int row = g >> 4;
    int d = (g & 15) << 2;
    float4 v = ((const float4*)src)[g];
    __half2 a = __halves2half2(__float2half_rn(v.x), __float2half_rn(v.y));
    __half2 b = __halves2half2(__float2half_rn(v.z), __float2half_rn(v.w));
    __half2* p = (__half2*)(dst + (size_t)row * KPAD + d);
    p[0] = a;
    p[1] = b;
}

// ---- main: two-loop fused attention, fp16 operands, log2-domain softmax -----
// smem: kh[2] @0/9216, vh[2] @18432/27648, qs @36864 (32KB) -> 68KB total
#define KH0 0
#define VH0 18432
#define QS_OFF 36864
#define SMEM_TOTAL 69632

__global__ __launch_bounds__(256, 2) void attn_fused(const float* __restrict__ Q,
                                                     float* __restrict__ ctx,
                                                     float* __restrict__ attn) {
    extern __shared__ char smem[];
    float* qs = (float*)(smem + QS_OFF);
    const uint32_t smem_b = sptr(smem);

    const int bh = blockIdx.x;
    const int qt = (int)gridDim.y - 1 - (int)blockIdx.y;  // heavy tiles first
    const int r0 = qt << 7;
    const float* Qb = Q + ((size_t)bh * NS + r0) * ND;
    const char* Kh = (const char*)(g_kh + (size_t)bh * NS * KPAD);
    const char* Vh = (const char*)(g_vh + (size_t)bh * NS * KPAD);
    const int tid = threadIdx.x;
    const int nsteps = (r0 + 128) >> 6;

    // load Q (scaled into log2 domain); prefetch K tile 0 into kh[0]
    for (int i = tid; i < 2048; i += 256) {
        float4 v = ((const float4*)Qb)[i];
        v.x *= QSCALE; v.y *= QSCALE; v.z *= QSCALE; v.w *= QSCALE;
        ((float4*)qs)[i] = v;
    }
    for (int i = tid; i < 576; i += 256)
        cpasync16(smem_b + KH0 + i * 16, Kh + i * 16);
    asm volatile("cp.async.commit_group;");
    __syncthreads();

    const int w = tid >> 5, L = tid & 31, g2 = L >> 2, t4 = L & 3, g3 = L >> 3, lr = L & 7;

    uint32_t Ah[4][4];
    {
        const int rA = (w << 4) + g2;
#pragma unroll
        for (int kc = 0; kc < 4; kc++) {
            int c0 = (kc << 4) + (t4 << 1);
            Ah[kc][0] = pack2(qs[rA * 64 + c0],           qs[rA * 64 + c0 + 1]);
            Ah[kc][1] = pack2(qs[(rA + 8) * 64 + c0],     qs[(rA + 8) * 64 + c0 + 1]);
            Ah[kc][2] = pack2(qs[rA * 64 + c0 + 8],       qs[rA * 64 + c0 + 9]);
            Ah[kc][3] = pack2(qs[(rA + 8) * 64 + c0 + 8], qs[(rA + 8) * 64 + c0 + 9]);
        }
    }

    const int row0 = r0 + (w << 4) + g2;
    const int row1 = row0 + 8;
    const int key_l = lr + ((g3 & 1) << 3);
    const int d_l = (g3 & 2) << 2;

    // ------------------ loop 1: Z only (K only, no stores) -------------------
    float zs0 = 0.f, zs1 = 0.f;
    for (int s = 0; s < nsteps; s++) {
        if (s + 1 < nsteps) {
            const uint32_t kb_s = smem_b + KH0 + ((s + 1) & 1) * 9216;
            const char* src = Kh + (size_t)((s + 1) << 6) * KPAD * 2;
            for (int i = tid; i < 576; i += 256)
                cpasync16(kb_s + i * 16, src + i * 16);
            asm volatile("cp.async.commit_group;");
            asm volatile("cp.async.wait_group 1;");
        } else {
            asm volatile("cp.async.wait_group 0;");
        }
        __syncthreads();

        const uint32_t khb = smem_b + KH0 + (s & 1) * 9216;
        const int k0 = s << 6;
#pragma unroll
        for (int np = 0; np < 4; np++) {
            float SvA[8] = {0.f, 0.f, 0.f, 0.f, 0.f, 0.f, 0.f, 0.f};
            float SvB[8] = {0.f, 0.f, 0.f, 0.f, 0.f, 0.f, 0.f, 0.f};
#pragma unroll
            for (int kc = 0; kc < 4; kc++) {
                uint32_t b0, b1, b2, b3;
                uint32_t off = (uint32_t)((np * 16 + key_l) * KPAD + (kc << 4) + d_l) * 2;
                ldsm4(b0, b1, b2, b3, khb + off);
                float* dst = (kc < 2) ? SvA : SvB;
                mma16816(dst,     Ah[kc], b0, b2);
                mma16816(dst + 4, Ah[kc], b1, b3);
            }
            const int kb = k0 + (np << 4) + (t4 << 1);
            if (kb + 9 <= row0) {
                zs0 += ex2(SvA[0] + SvB[0]) + ex2(SvA[1] + SvB[1])
                     + ex2(SvA[4] + SvB[4]) + ex2(SvA[5] + SvB[5]);
                zs1 += ex2(SvA[2] + SvB[2]) + ex2(SvA[3] + SvB[3])
                     + ex2(SvA[6] + SvB[6]) + ex2(SvA[7] + SvB[7]);
            } else {
                float p;
                p = (kb     <= row0) ? ex2(SvA[0] + SvB[0]) : 0.f; zs0 += p;
                p = (kb + 1 <= row0) ? ex2(SvA[1] + SvB[1]) : 0.f; zs0 += p;
                p = (kb     <= row1) ? ex2(SvA[2] + SvB[2]) : 0.f; zs1 += p;
                p = (kb + 1 <= row1) ? ex2(SvA[3] + SvB[3]) : 0.f; zs1 += p;
                p = (kb + 8 <= row0) ? ex2(SvA[4] + SvB[4]) : 0.f; zs0 += p;
                p = (kb + 9 <= row0) ? ex2(SvA[5] + SvB[5]) : 0.f; zs0 += p;
                p = (kb + 8 <= row1) ? ex2(SvA[6] + SvB[6]) : 0.f; zs1 += p;
                p = (kb + 9 <= row1) ? ex2(SvA[7] + SvB[7]) : 0.f; zs1 += p;
            }
        }
        __syncthreads();
    }

    zs0 += __shfl_xor_sync(0xffffffffu, zs0, 1);
    zs0 += __shfl_xor_sync(0xffffffffu, zs0, 2);
    zs1 += __shfl_xor_sync(0xffffffffu, zs1, 1);
    zs1 += __shfl_xor_sync(0xffffffffu, zs1, 2);
    const float l2z0 = -__log2f(zs0);   // log2(1/Z)
    const float l2z1 = -__log2f(zs1);

    float* arow0 = attn + ((size_t)bh * NS + row0) * NS;
    float* arow1 = attn + ((size_t)bh * NS + row1) * NS;

    float Ov[8][4];
#pragma unroll
    for (int i = 0; i < 8; i++)
#pragma unroll
        for (int j = 0; j < 4; j++) Ov[i][j] = 0.f;

    // prefetch K+V tile 0 for loop 2
    for (int i = tid; i < 1152; i += 256) {
        if (i < 576) cpasync16(smem_b + KH0 + i * 16, Kh + i * 16);
        else         cpasync16(smem_b + VH0 + (i - 576) * 16, Vh + (i - 576) * 16);
    }
    asm volatile("cp.async.commit_group;");

    // ------------- loop 2: emit normalized P, accumulate O -------------------
    for (int s = 0; s < nsteps; s++) {
        if (s + 1 < nsteps) {
            const int b1i = (s + 1) & 1;
            const char* ksrc = Kh + (size_t)((s + 1) << 6) * KPAD * 2;
            const char* vsrc = Vh + (size_t)((s + 1) << 6) * KPAD * 2;
            for (int i = tid; i < 1152; i += 256) {
                if (i < 576) cpasync16(smem_b + KH0 + b1i * 9216 + i * 16, ksrc + i * 16);
                else         cpasync16(smem_b + VH0 + b1i * 9216 + (i - 576) * 16, vsrc + (i - 576) * 16);
            }
            asm volatile("cp.async.commit_group;");
            asm volatile("cp.async.wait_group 1;");
        } else {
            asm volatile("cp.async.wait_group 0;");
        }
        __syncthreads();

        const uint32_t khb = smem_b + KH0 + (s & 1) * 9216;
        const uint32_t vhb = smem_b + VH0 + (s & 1) * 9216;
        const int k0 = s << 6;
#pragma unroll
        for (int np = 0; np < 4; np++) {
            float Sv[8];
            Sv[0] = Sv[1] = l2z0; Sv[2] = Sv[3] = l2z1;
            Sv[4] = Sv[5] = l2z0; Sv[6] = Sv[7] = l2z1;
#pragma unroll
            for (int kc = 0; kc < 4; kc++) {
                uint32_t b0, b1, b2, b3;
                uint32_t off = (uint32_t)((np * 16 + key_l) * KPAD + (kc << 4) + d_l) * 2;
                ldsm4(b0, b1, b2, b3, khb + off);
                mma16816(Sv,     Ah[kc], b0, b2);
                mma16816(Sv + 4, Ah[kc], b1, b3);
            }
            const int kb = k0 + (np << 4) + (t4 << 1);
            float p0, p1, p2, p3, p4, p5, p6, p7;
            if (kb + 9 <= row0) {
                p0 = ex2(Sv[0]); p1 = ex2(Sv[1]);
                p2 = ex2(Sv[2]); p3 = ex2(Sv[3]);
                p4 = ex2(Sv[4]); p5 = ex2(Sv[5]);
                p6 = ex2(Sv[6]); p7 = ex2(Sv[7]);
            } else {
                p0 = (kb     <= row0) ? ex2(Sv[0]) : 0.f;
                p1 = (kb + 1 <= row0) ? ex2(Sv[1]) : 0.f;
                p2 = (kb     <= row1) ? ex2(Sv[2]) : 0.f;
                p3 = (kb + 1 <= row1) ? ex2(Sv[3]) : 0.f;
                p4 = (kb + 8 <= row0) ? ex2(Sv[4]) : 0.f;
                p5 = (kb + 9 <= row0) ? ex2(Sv[5]) : 0.f;
                p6 = (kb + 8 <= row1) ? ex2(Sv[6]) : 0.f;
                p7 = (kb + 9 <= row1) ? ex2(Sv[7]) : 0.f;
            }

            stcs2(arow0 + kb,     p0, p1);
            stcs2(arow1 + kb,     p2, p3);
            stcs2(arow0 + kb + 8, p4, p5);
            stcs2(arow1 + kb + 8, p6, p7);

            uint32_t Ph[4];
            Ph[0] = pack2(p0, p1);
            Ph[1] = pack2(p2, p3);
            Ph[2] = pack2(p4, p5);
            Ph[3] = pack2(p6, p7);

#pragma unroll
            for (int dd = 0; dd < 4; dd++) {
                uint32_t v0, v1, v2, v3;
                uint32_t off = (uint32_t)((np * 16 + key_l) * KPAD + (dd << 4) + d_l) * 2;
                ldsm4t(v0, v1, v2, v3, vhb + off);
                mma16816(Ov[2 * dd],     Ph, v0, v1);
                mma16816(Ov[2 * dd + 1], Ph, v2, v3);
            }
        }
        __syncthreads();
    }

    // write context (P already normalized)
    {
        float* crow0 = ctx + ((size_t)bh * NS + row0) * ND;
        float* crow1 = ctx + ((size_t)bh * NS + row1) * ND;
#pragma unroll
        for (int dt = 0; dt < 8; dt++) {
            int c = (dt << 3) + (t4 << 1);
            *(float2*)(crow0 + c) = make_float2(Ov[dt][0], Ov[dt][1]);
            *(float2*)(crow1 + c) = make_float2(Ov[dt][2], Ov[dt][3]);
        }
    }

    // zero-fill masked region beyond the causal band (streaming stores)
    {
        const int ks = (qt + 1) << 7;
        if (ks < NS) {
            const int width4 = (NS - ks) >> 2;
            float4 z4 = make_float4(0.f, 0.f, 0.f, 0.f);
            float* abase = attn + ((size_t)bh * NS + r0) * NS + ks;
            const int total = 128 * width4;
            for (int i = tid; i < total; i += 256) {
                int row = i / width4;
                int c = i - row * width4;
                stcs4(abase + (size_t)row * NS + (c << 2), z4);
            }
        }
    }
}

extern "C" void kernel_launch(void* const* d_in, const int* in_sizes, int n_in,
                              void* d_out, int out_size) {
    const float* Q = (const float*)d_in[0];
    const float* K = (const float*)d_in[1];
    const float* V = (const float*)d_in[2];
    float* ctx = (float*)d_out;
    float* attn = (float*)d_out + (size_t)NB * NH * NS * ND;

    static bool attr_set = false;
    if (!attr_set) {
        cudaFuncSetAttribute(attn_fused, cudaFuncAttributeMaxDynamicSharedMemorySize, SMEM_TOTAL);
        attr_set = true;
    }

    // pre-pass: convert K/V to fp16 padded scratch
    cvt_kv<<<2 * NB * NH * NS * (ND / 4) / 256, 256>>>(K, V);

    dim3 grid(NB * NH, NS / 128);
    dim3 block(256);
    attn_fused<<<grid, block, SMEM_TOTAL>>>(Q, ctx, attn);
}

// round 17
// speedup vs baseline: 1.1338x; 1.0223x over previous
#include <cuda_runtime.h>
#include <cuda_fp16.h>
#include <cstdint>
#include <cstddef>

#define NB 4
#define NH 16
#define NS 2048
#define ND 64
#define KPAD 72
#define QSCALE 0.18033688011112042f   // 0.125 * log2(e): scores in log2 domain

// fp16 K/V scratch, padded to 72 halves per row (144 B = 9 x 16B chunks)
__device__ __half g_kh[(size_t)NB * NH * NS * KPAD];
__device__ __half g_vh[(size_t)NB * NH * NS * KPAD];

// smem: kh[4] @0 (4x9216), vh[4] @36864 (4x9216); qs overlays vh region
#define KH_OFF 0
#define VH_OFF 36864
#define QS_OFF 36864
#define SMEM_TOTAL 73728

static __device__ __forceinline__ uint32_t sptr(const void* p) {
    return (uint32_t)__cvta_generic_to_shared(p);
}
static __device__ __forceinline__ void cpasync16(uint32_t dst, const void* src) {
    asm volatile("cp.async.cg.shared.global [%0], [%1], 16;" :: "r"(dst), "l"(src));
}
static __device__ __forceinline__ float ex2(float x) {
    float r;
    asm("ex2.approx.ftz.f32 %0, %1;" : "=f"(r) : "f"(x));
    return r;
}
static __device__ __forceinline__ void ldsm4(uint32_t& r0, uint32_t& r1, uint32_t& r2, uint32_t& r3, uint32_t a) {
    asm volatile("ldmatrix.sync.aligned.m8n8.x4.shared.b16 {%0,%1,%2,%3},[%4];"
                 : "=r"(r0), "=r"(r1), "=r"(r2), "=r"(r3) : "r"(a));
}
static __device__ __forceinline__ void ldsm4t(uint32_t& r0, uint32_t& r1, uint32_t& r2, uint32_t& r3, uint32_t a) {
    asm volatile("ldmatrix.sync.aligned.m8n8.x4.trans.shared.b16 {%0,%1,%2,%3},[%4];"
                 : "=r"(r0), "=r"(r1), "=r"(r2), "=r"(r3) : "r"(a));
}
static __device__ __forceinline__ void mma16816(float* d, const uint32_t* a, uint32_t b0, uint32_t b1) {
    asm volatile(
        "mma.sync.aligned.m16n8k16.row.col.f32.f16.f16.f32 "
        "{%0,%1,%2,%3},{%4,%5,%6,%7},{%8,%9},{%0,%1,%2,%3};"
        : "+f"(d[0]), "+f"(d[1]), "+f"(d[2]), "+f"(d[3])
        : "r"(a[0]), "r"(a[1]), "r"(a[2]), "r"(a[3]), "r"(b0), "r"(b1));
}
static __device__ __forceinline__ uint32_t pack2(float a, float b) {
    __half2 h = __halves2half2(__float2half_rn(a), __float2half_rn(b));
    return *(uint32_t*)&h;
}
static __device__ __forceinline__ void stcs2(float* p, float a, float b) {
    asm volatile("st.global.cs.v2.f32 [%0], {%1,%2};" :: "l"(p), "f"(a), "f"(b) : "memory");
}
static __device__ __forceinline__ void stcs4(float* p, float4 v) {
    asm volatile("st.global.cs.v4.f32 [%0], {%1,%2,%3,%4};"
                 :: "l"(p), "f"(v.x), "f"(v.y), "f"(v.z), "f"(v.w) : "memory");
}

// ---- pre-pass: fp32 K/V -> fp16 padded scratch ------------------------------
__global__ __launch_bounds__(256) void cvt_kv(const float* __restrict__ K,
                                              const float* __restrict__ V) {
    const int per_tensor = NB * NH * NS * (ND / 4);
    int idx = blockIdx.x * 256 + threadIdx.x;
    const float* src;
    __half* dst;
    int g;
    if (idx < per_tensor) { src = K; dst = g_kh; g = idx; }
    else                  { src = V; dst = g_vh; g = idx - per_tensor; }
    int row = g >> 4;
    int d = (g & 15) << 2;
    float4 v = ((const float4*)src)[g];
    __half2 a = __halves2half2(__float2half_rn(v.x), __float2half_rn(v.y));
    __half2 b = __halves2half2(__float2half_rn(v.z), __float2half_rn(v.w));
    __half2* p = (__half2*)(dst + (size_t)row * KPAD + d);
    p[0] = a;
    p[1] = b;
}

// ---- main: two-loop fused attention, fp16 operands, log2-domain softmax -----
// 4-deep circular K/V smem buffers, prefetch distance 2, one barrier per tile.
__global__ __launch_bounds__(256, 2) void attn_fused(const float* __restrict__ Q,
                                                     float* __restrict__ ctx,
                                                     float* __restrict__ attn) {
    extern __shared__ char smem[];
    float* qs = (float*)(smem + QS_OFF);
    const uint32_t smem_b = sptr(smem);

    const int bh = blockIdx.x;
    const int qt = (int)gridDim.y - 1 - (int)blockIdx.y;  // heavy tiles first
    const int r0 = qt << 7;
    const float* Qb = Q + ((size_t)bh * NS + r0) * ND;
    const char* Kh = (const char*)(g_kh + (size_t)bh * NS * KPAD);
    const char* Vh = (const char*)(g_vh + (size_t)bh * NS * KPAD);
    const int tid = threadIdx.x;
    const int nsteps = (r0 + 128) >> 6;   // always >= 2

    // load Q (scaled into log2 domain) into qs
    for (int i = tid; i < 2048; i += 256) {
        float4 v = ((const float4*)Qb)[i];
        v.x *= QSCALE; v.y *= QSCALE; v.z *= QSCALE; v.w *= QSCALE;
        ((float4*)qs)[i] = v;
    }
    // pre-issue K tiles 0 and 1
#pragma unroll
    for (int t = 0; t < 2; t++) {
        const char* src = Kh + (size_t)(t << 6) * KPAD * 2;
        for (int i = tid; i < 576; i += 256)
            cpasync16(smem_b + KH_OFF + t * 9216 + i * 16, src + i * 16);
        asm volatile("cp.async.commit_group;");
    }
    __syncthreads();

    const int w = tid >> 5, L = tid & 31, g2 = L >> 2, t4 = L & 3, g3 = L >> 3, lr = L & 7;

    uint32_t Ah[4][4];
    {
        const int rA = (w << 4) + g2;
#pragma unroll
        for (int kc = 0; kc < 4; kc++) {
            int c0 = (kc << 4) + (t4 << 1);
            Ah[kc][0] = pack2(qs[rA * 64 + c0],           qs[rA * 64 + c0 + 1]);
            Ah[kc][1] = pack2(qs[(rA + 8) * 64 + c0],     qs[(rA + 8) * 64 + c0 + 1]);
            Ah[kc][2] = pack2(qs[rA * 64 + c0 + 8],       qs[rA * 64 + c0 + 9]);
            Ah[kc][3] = pack2(qs[(rA + 8) * 64 + c0 + 8], qs[(rA + 8) * 64 + c0 + 9]);
        }
    }

    const int row0 = r0 + (w << 4) + g2;
    const int row1 = row0 + 8;
    const int key_l = lr + ((g3 & 1) << 3);
    const int d_l = (g3 & 2) << 2;

    // ------------------ loop 1: Z only (K only, no stores) -------------------
    float zs0 = 0.f, zs1 = 0.f;
    for (int s = 0; s < nsteps; s++) {
        if (s + 2 < nsteps) {
            const char* src = Kh + (size_t)((s + 2) << 6) * KPAD * 2;
            const uint32_t dst = smem_b + KH_OFF + ((s + 2) & 3) * 9216;
            for (int i = tid; i < 576; i += 256)
                cpasync16(dst + i * 16, src + i * 16);
        }
        asm volatile("cp.async.commit_group;");
        asm volatile("cp.async.wait_group 2;");
        __syncthreads();

        const uint32_t khb = smem_b + KH_OFF + (s & 3) * 9216;
        const int k0 = s << 6;
#pragma unroll
        for (int np = 0; np < 4; np++) {
            float SvA[8] = {0.f, 0.f, 0.f, 0.f, 0.f, 0.f, 0.f, 0.f};
            float SvB[8] = {0.f, 0.f, 0.f, 0.f, 0.f, 0.f, 0.f, 0.f};
#pragma unroll
            for (int kc = 0; kc < 4; kc++) {
                uint32_t b0, b1, b2, b3;
                uint32_t off = (uint32_t)((np * 16 + key_l) * KPAD + (kc << 4) + d_l) * 2;
                ldsm4(b0, b1, b2, b3, khb + off);
                float* dst = (kc < 2) ? SvA : SvB;
                mma16816(dst,     Ah[kc], b0, b2);
                mma16816(dst + 4, Ah[kc], b1, b3);
            }
            const int kb = k0 + (np << 4) + (t4 << 1);
            if (kb + 9 <= row0) {
                zs0 += ex2(SvA[0] + SvB[0]) + ex2(SvA[1] + SvB[1])
                     + ex2(SvA[4] + SvB[4]) + ex2(SvA[5] + SvB[5]);
                zs1 += ex2(SvA[2] + SvB[2]) + ex2(SvA[3] + SvB[3])
                     + ex2(SvA[6] + SvB[6]) + ex2(SvA[7] + SvB[7]);
            } else {
                float p;
                p = (kb     <= row0) ? ex2(SvA[0] + SvB[0]) : 0.f; zs0 += p;
                p = (kb + 1 <= row0) ? ex2(SvA[1] + SvB[1]) : 0.f; zs0 += p;
                p = (kb     <= row1) ? ex2(SvA[2] + SvB[2]) : 0.f; zs1 += p;
                p = (kb + 1 <= row1) ? ex2(SvA[3] + SvB[3]) : 0.f; zs1 += p;
                p = (kb + 8 <= row0) ? ex2(SvA[4] + SvB[4]) : 0.f; zs0 += p;
                p = (kb + 9 <= row0) ? ex2(SvA[5] + SvB[5]) : 0.f; zs0 += p;
                p = (kb + 8 <= row1) ? ex2(SvA[6] + SvB[6]) : 0.f; zs1 += p;
                p = (kb + 9 <= row1) ? ex2(SvA[7] + SvB[7]) : 0.f; zs1 += p;
            }
        }
    }

    zs0 += __shfl_xor_sync(0xffffffffu, zs0, 1);
    zs0 += __shfl_xor_sync(0xffffffffu, zs0, 2);
    zs1 += __shfl_xor_sync(0xffffffffu, zs1, 1);
    zs1 += __shfl_xor_sync(0xffffffffu, zs1, 2);
    const float l2z0 = -__log2f(zs0);   // log2(1/Z)
    const float l2z1 = -__log2f(zs1);

    // all warps done with loop-1 buffers before loop-2 pre-issue reuses them
    __syncthreads();

    float* arow0 = attn + ((size_t)bh * NS + row0) * NS;
    float* arow1 = attn + ((size_t)bh * NS + row1) * NS;

    float Ov[8][4];
#pragma unroll
    for (int i = 0; i < 8; i++)
#pragma unroll
        for (int j = 0; j < 4; j++) Ov[i][j] = 0.f;

    // pre-issue K+V tiles 0 and 1 for loop 2
#pragma unroll
    for (int t = 0; t < 2; t++) {
        const char* ksrc = Kh + (size_t)(t << 6) * KPAD * 2;
        const char* vsrc = Vh + (size_t)(t << 6) * KPAD * 2;
        for (int i = tid; i < 576; i += 256) {
            cpasync16(smem_b + KH_OFF + t * 9216 + i * 16, ksrc + i * 16);
            cpasync16(smem_b + VH_OFF + t * 9216 + i * 16, vsrc + i * 16);
        }
        asm volatile("cp.async.commit_group;");
    }

    // ------------- loop 2: emit normalized P, accumulate O -------------------
    for (int s = 0; s < nsteps; s++) {
        if (s + 2 < nsteps) {
            const char* ksrc = Kh + (size_t)((s + 2) << 6) * KPAD * 2;
            const char* vsrc = Vh + (size_t)((s + 2) << 6) * KPAD * 2;
            const uint32_t kdst = smem_b + KH_OFF + ((s + 2) & 3) * 9216;
            const uint32_t vdst = smem_b + VH_OFF + ((s + 2) & 3) * 9216;
            for (int i = tid; i < 576; i += 256) {
                cpasync16(kdst + i * 16, ksrc + i * 16);
                cpasync16(vdst + i * 16, vsrc + i * 16);
            }
        }
        asm volatile("cp.async.commit_group;");
        asm volatile("cp.async.wait_group 2;");
        __syncthreads();

        const uint32_t khb = smem_b + KH_OFF + (s & 3) * 9216;
        const uint32_t vhb = smem_b + VH_OFF + (s & 3) * 9216;
        const int k0 = s << 6;
#pragma unroll
        for (int np = 0; np < 4; np++) {
            float Sv[8];
            Sv[0] = Sv[1] = l2z0; Sv[2] = Sv[3] = l2z1;
            Sv[4] = Sv[5] = l2z0; Sv[6] = Sv[7] = l2z1;
            float SvB[8] = {0.f, 0.f, 0.f, 0.f, 0.f, 0.f, 0.f, 0.f};
#pragma unroll
            for (int kc = 0; kc < 4; kc++) {
                uint32_t b0, b1, b2, b3;
                uint32_t off = (uint32_t)((np * 16 + key_l) * KPAD + (kc << 4) + d_l) * 2;
                ldsm4(b0, b1, b2, b3, khb + off);
                float* dst = (kc < 2) ? Sv : SvB;
                mma16816(dst,     Ah[kc], b0, b2);
                mma16816(dst + 4, Ah[kc], b1, b3);
            }
            const int kb = k0 + (np << 4) + (t4 << 1);
            float p0, p1, p2, p3, p4, p5, p6, p7;
            if (kb + 9 <= row0) {
                p0 = ex2(Sv[0] + SvB[0]); p1 = ex2(Sv[1] + SvB[1]);
                p2 = ex2(Sv[2] + SvB[2]); p3 = ex2(Sv[3] + SvB[3]);
                p4 = ex2(Sv[4] + SvB[4]); p5 = ex2(Sv[5] + SvB[5]);
                p6 = ex2(Sv[6] + SvB[6]); p7 = ex2(Sv[7] + SvB[7]);
            } else {
                p0 = (kb     <= row0) ? ex2(Sv[0] + SvB[0]) : 0.f;
                p1 = (kb + 1 <= row0) ? ex2(Sv[1] + SvB[1]) : 0.f;
                p2 = (kb     <= row1) ? ex2(Sv[2] + SvB[2]) : 0.f;
                p3 = (kb + 1 <= row1) ? ex2(Sv[3] + SvB[3]) : 0.f;
                p4 = (kb + 8 <= row0) ? ex2(Sv[4] + SvB[4]) : 0.f;
                p5 = (kb + 9 <= row0) ? ex2(Sv[5] + SvB[5]) : 0.f;
                p6 = (kb + 8 <= row1) ? ex2(Sv[6] + SvB[6]) : 0.f;
                p7 = (kb + 9 <= row1) ? ex2(Sv[7] + SvB[7]) : 0.f;
            }

            stcs2(arow0 + kb,     p0, p1);
            stcs2(arow1 + kb,     p2, p3);
            stcs2(arow0 + kb + 8, p4, p5);
            stcs2(arow1 + kb + 8, p6, p7);

            uint32_t Ph[4];
            Ph[0] = pack2(p0, p1);
            Ph[1] = pack2(p2, p3);
            Ph[2] = pack2(p4, p5);
            Ph[3] = pack2(p6, p7);

#pragma unroll
            for (int dd = 0; dd < 4; dd++) {
                uint32_t v0, v1, v2, v3;
                uint32_t off = (uint32_t)((np * 16 + key_l) * KPAD + (dd << 4) + d_l) * 2;
                ldsm4t(v0, v1, v2, v3, vhb + off);
                mma16816(Ov[2 * dd],     Ph, v0, v1);
                mma16816(Ov[2 * dd + 1], Ph, v2, v3);
            }
        }
    }

    // write context (P already normalized)
    {
        float* crow0 = ctx + ((size_t)bh * NS + row0) * ND;
        float* crow1 = ctx + ((size_t)bh * NS + row1) * ND;
#pragma unroll
        for (int dt = 0; dt < 8; dt++) {
            int c = (dt << 3) + (t4 << 1);
            *(float2*)(crow0 + c) = make_float2(Ov[dt][0], Ov[dt][1]);
            *(float2*)(crow1 + c) = make_float2(Ov[dt][2], Ov[dt][3]);
        }
    }

    // zero-fill masked region beyond the causal band (streaming stores)
    {
        const int ks = (qt + 1) << 7;
        if (ks < NS) {
            const int width4 = (NS - ks) >> 2;
            float4 z4 = make_float4(0.f, 0.f, 0.f, 0.f);
            float* abase = attn + ((size_t)bh * NS + r0) * NS + ks;
            const int total = 128 * width4;
            for (int i = tid; i < total; i += 256) {
                int row = i / width4;
                int c = i - row * width4;
                stcs4(abase + (size_t)row * NS + (c << 2), z4);
            }
        }
    }
}

extern "C" void kernel_launch(void* const* d_in, const int* in_sizes, int n_in,
                              void* d_out, int out_size) {
    const float* Q = (const float*)d_in[0];
    const float* K = (const float*)d_in[1];
    const float* V = (const float*)d_in[2];
    float* ctx = (float*)d_out;
    float* attn = (float*)d_out + (size_t)NB * NH * NS * ND;

    static bool attr_set = false;
    if (!attr_set) {
        cudaFuncSetAttribute(attn_fused, cudaFuncAttributeMaxDynamicSharedMemorySize, SMEM_TOTAL);
        attr_set = true;
    }

    // pre-pass: convert K/V to fp16 padded scratch
    cvt_kv<<<2 * NB * NH * NS * (ND / 4) / 256, 256>>>(K, V);

    dim3 grid(NB * NH, NS / 128);
    dim3 block(256);
    attn_fused<<<grid, block, SMEM_TOTAL>>>(Q, ctx, attn);
}